// round 11
// baseline (speedup 1.0000x reference)
#include <cuda_runtime.h>
#include <cuda_fp16.h>
#include <math.h>
#include <stdint.h>

#define H 1024
#define F 2048
#define E 8
#define T 2048

// gemm1: block 128x64, 4 warps (2m x 2n), warp 64x32 dual
#define BM 128
#define BN 64
#define BK 32
// gemm2: block 128x128, 4 warps (2m x 2n), warp 64x64
#define BM2 128
#define BN2 128
#define BK2 32
#define SPH 40    // smem row stride in halfs = 80B, 16B-aligned, ldmatrix conflict-free

// gemm1 smem (halfs): A[2][128*40], B1[2][64*40], B3[2][64*40]
#define G1_AST (BM * SPH)
#define G1_BST (BN * SPH)
#define G1_A(s)  ((s) * G1_AST)
#define G1_B1(s) (2 * G1_AST + (s) * G1_BST)
#define G1_B3(s) (2 * G1_AST + 2 * G1_BST + (s) * G1_BST)
#define G1_BYTES ((2 * G1_AST + 4 * G1_BST) * 2)    // 40960
// gemm2 smem (halfs): A[2][128*40], B[2][128*40]
#define G2_AST (BM2 * SPH)
#define G2_A(s)  ((s) * G2_AST)
#define G2_B(s)  (2 * G2_AST + (s) * G2_AST)
#define G2_BYTES ((4 * G2_AST) * 2)                 // 40960

// ---- scratch ----
__device__ int    g_cnt[E];
__device__ int    g_tok[E * T];
__device__ float  g_wgt[E * T];
__device__ __half g_x16[(size_t)T * H];
__device__ __half g_mid[(size_t)E * T * F];

// ---------------------------------------------------------------
__device__ __forceinline__ void ldsm4(unsigned r[4], const __half* p) {
    unsigned a = (unsigned)__cvta_generic_to_shared(p);
    asm volatile("ldmatrix.sync.aligned.m8n8.x4.shared.b16 {%0,%1,%2,%3}, [%4];"
                 : "=r"(r[0]), "=r"(r[1]), "=r"(r[2]), "=r"(r[3]) : "r"(a));
}
__device__ __forceinline__ void mma16(float c[4], const unsigned a[4], unsigned b0, unsigned b1) {
    asm volatile(
        "mma.sync.aligned.m16n8k16.row.col.f32.f16.f16.f32 "
        "{%0,%1,%2,%3},{%4,%5,%6,%7},{%8,%9},{%0,%1,%2,%3};"
        : "+f"(c[0]), "+f"(c[1]), "+f"(c[2]), "+f"(c[3])
        : "r"(a[0]), "r"(a[1]), "r"(a[2]), "r"(a[3]), "r"(b0), "r"(b1));
}
__device__ __forceinline__ uint2 f4h(float4 v) {
    __half2 lo = __floats2half2_rn(v.x, v.y);
    __half2 hi = __floats2half2_rn(v.z, v.w);
    uint2 r;
    r.x = *(unsigned*)&lo; r.y = *(unsigned*)&hi;
    return r;
}
__device__ __forceinline__ void cp_async16(const __half* sdst, const __half* gsrc) {
    unsigned d = (unsigned)__cvta_generic_to_shared(sdst);
    asm volatile("cp.async.cg.shared.global [%0], [%1], 16;" :: "r"(d), "l"(gsrc));
}
#define CP_COMMIT() asm volatile("cp.async.commit_group;" ::: "memory")
#define CP_WAIT0()  asm volatile("cp.async.wait_group 0;" ::: "memory")

// ---------------------------------------------------------------
__global__ void zero_cnt_kernel() {
    if (threadIdx.x < E) g_cnt[threadIdx.x] = 0;
}

// ---------------------------------------------------------------
// Router (fused x fp32->fp16 copy): one warp per token.
__global__ __launch_bounds__(256) void router_kernel(
    const float* __restrict__ x, const float* __restrict__ gw,
    float* __restrict__ logits_out)
{
    const int t    = blockIdx.x * 8 + (threadIdx.x >> 5);
    const int lane = threadIdx.x & 31;
    const float4* xr  = (const float4*)(x + (size_t)t * H);
    const float4* gw4 = (const float4*)gw;
    __half* xo = g_x16 + (size_t)t * H;

    float acc[E];
#pragma unroll
    for (int e = 0; e < E; e++) acc[e] = 0.f;

#pragma unroll
    for (int i = 0; i < 8; i++) {
        float4 xv = xr[i * 32 + lane];
        *(uint2*)(xo + (i * 32 + lane) * 4) = f4h(xv);
#pragma unroll
        for (int e = 0; e < E; e++) {
            float4 g = gw4[e * 256 + i * 32 + lane];
            acc[e] += xv.x * g.x + xv.y * g.y + xv.z * g.z + xv.w * g.w;
        }
    }
#pragma unroll
    for (int e = 0; e < E; e++)
#pragma unroll
        for (int o = 16; o > 0; o >>= 1)
            acc[e] += __shfl_xor_sync(0xffffffffu, acc[e], o);

    if (lane == 0) {
        if (logits_out)
#pragma unroll
            for (int e = 0; e < E; e++) logits_out[(size_t)t * E + e] = acc[e];
        int i1 = 0;
#pragma unroll
        for (int e = 1; e < E; e++) if (acc[e] > acc[i1]) i1 = e;
        int i2 = -1;
#pragma unroll
        for (int e = 0; e < E; e++) {
            if (e == i1) continue;
            if (i2 < 0 || acc[e] > acc[i2]) i2 = e;
        }
        float wa = 1.f / (1.f + expf(acc[i2] - acc[i1]));
        float wb = 1.f - wa;
        int s1 = atomicAdd(&g_cnt[i1], 1);
        g_tok[i1 * T + s1] = t; g_wgt[i1 * T + s1] = wa;
        int s2 = atomicAdd(&g_cnt[i2], 1);
        g_tok[i2 * T + s2] = t; g_wgt[i2 * T + s2] = wb;
    }
}

// ---------------------------------------------------------------
// GEMM1: block 128x64, 128 thr, 4 warps (2m x 2n), warp 64x32 dual (w1,w3).
__global__ __launch_bounds__(128, 2) void gemm1_kernel(
    const float* __restrict__ w1,
    const float* __restrict__ w3)
{
    extern __shared__ __align__(16) __half sm[];
    const int e  = blockIdx.z;
    const int n0 = blockIdx.x * BN;
    const int m0 = blockIdx.y * BM;
    const int ne = g_cnt[e];
    if (m0 >= ne) return;

    const int tid  = threadIdx.x;
    const int lane = tid & 31, wid = tid >> 5;
    const int wm   = (wid & 1) * 64, wn = (wid >> 1) * 32;

    // A loader (cp.async, 4 granules/thread): row = i*32 + tid>>2, col8 = (tid&3)*8
    const int ar = tid >> 2, ac8 = (tid & 3) * 8;
    const __half* amp[4];
#pragma unroll
    for (int r = 0; r < 4; r++) {
        int m = m0 + ar + 32 * r;
        int idx = (m < ne) ? m : (ne - 1);
        amp[r] = g_x16 + (size_t)g_tok[e * T + idx] * H + ac8;
    }
    // B loaders (two waves of 32 rows): row = tid>>2 (+32w), colbase = (tid&3)*8; 2 f4 each
    const int br = tid >> 2, bcb = (tid & 3) * 8;
    const float* b1p = w1 + ((size_t)e * F + n0 + br) * H + bcb;
    const float* b3p = w3 + ((size_t)e * F + n0 + br) * H + bcb;
    const size_t bw = (size_t)32 * H;   // wave-1 row offset

    float4 v1a, v1b, v3a, v3b;
    float acc1[4][4][4] = {}, acc3[4][4][4] = {};

    // ---- prologue: stage 0 ----
#pragma unroll
    for (int r = 0; r < 4; r++)
        cp_async16(&sm[G1_A(0) + (ar + 32 * r) * SPH + ac8], amp[r]);
    CP_COMMIT();
#pragma unroll
    for (int w = 0; w < 2; w++) {
        v1a = *(const float4*)(b1p + w * bw);
        v1b = *(const float4*)(b1p + w * bw + 4);
        v3a = *(const float4*)(b3p + w * bw);
        v3b = *(const float4*)(b3p + w * bw + 4);
        *(uint2*)&sm[G1_B1(0) + (br + 32 * w) * SPH + bcb]     = f4h(v1a);
        *(uint2*)&sm[G1_B1(0) + (br + 32 * w) * SPH + bcb + 4] = f4h(v1b);
        *(uint2*)&sm[G1_B3(0) + (br + 32 * w) * SPH + bcb]     = f4h(v3a);
        *(uint2*)&sm[G1_B3(0) + (br + 32 * w) * SPH + bcb + 4] = f4h(v3b);
    }
    CP_WAIT0();
    __syncthreads();

    const int NC = H / BK;   // 32
    int cur = 0;
    for (int c = 0; c < NC; c++) {
        const int  nxt  = cur ^ 1;
        const bool more = (c + 1 < NC);
        int k0 = (c + 1) * BK;
        if (more) {
#pragma unroll
            for (int r = 0; r < 4; r++)
                cp_async16(&sm[G1_A(nxt) + (ar + 32 * r) * SPH + ac8], amp[r] + k0);
            CP_COMMIT();
            v1a = *(const float4*)(b1p + k0);
            v1b = *(const float4*)(b1p + k0 + 4);
            v3a = *(const float4*)(b3p + k0);
            v3b = *(const float4*)(b3p + k0 + 4);
        }

        // ---- compute kk=0 ----
        {
            unsigned a[4][4];
#pragma unroll
            for (int mt = 0; mt < 4; mt++)
                ldsm4(a[mt], &sm[G1_A(cur) + (wm + mt * 16 + (lane & 15)) * SPH + (lane >> 4) * 8]);
            unsigned b1f[2][4], b3f[2][4];
#pragma unroll
            for (int bh = 0; bh < 2; bh++) {
                int row = wn + bh * 16 + ((lane >> 4) & 1) * 8 + (lane & 7);
                int col = ((lane >> 3) & 1) * 8;
                ldsm4(b1f[bh], &sm[G1_B1(cur) + row * SPH + col]);
                ldsm4(b3f[bh], &sm[G1_B3(cur) + row * SPH + col]);
            }
#pragma unroll
            for (int mt = 0; mt < 4; mt++)
#pragma unroll
                for (int nt = 0; nt < 4; nt++) {
                    int bh = nt >> 1, pr = (nt & 1) * 2;
                    mma16(acc1[mt][nt], a[mt], b1f[bh][pr], b1f[bh][pr + 1]);
                    mma16(acc3[mt][nt], a[mt], b3f[bh][pr], b3f[bh][pr + 1]);
                }
        }

        if (more) {
            // store wave0, load wave1
            *(uint2*)&sm[G1_B1(nxt) + br * SPH + bcb]     = f4h(v1a);
            *(uint2*)&sm[G1_B1(nxt) + br * SPH + bcb + 4] = f4h(v1b);
            *(uint2*)&sm[G1_B3(nxt) + br * SPH + bcb]     = f4h(v3a);
            *(uint2*)&sm[G1_B3(nxt) + br * SPH + bcb + 4] = f4h(v3b);
            v1a = *(const float4*)(b1p + bw + k0);
            v1b = *(const float4*)(b1p + bw + k0 + 4);
            v3a = *(const float4*)(b3p + bw + k0);
            v3b = *(const float4*)(b3p + bw + k0 + 4);
        }

        // ---- compute kk=16 ----
        {
            unsigned a[4][4];
#pragma unroll
            for (int mt = 0; mt < 4; mt++)
                ldsm4(a[mt], &sm[G1_A(cur) + (wm + mt * 16 + (lane & 15)) * SPH + 16 + (lane >> 4) * 8]);
            unsigned b1f[2][4], b3f[2][4];
#pragma unroll
            for (int bh = 0; bh < 2; bh++) {
                int row = wn + bh * 16 + ((lane >> 4) & 1) * 8 + (lane & 7);
                int col = 16 + ((lane >> 3) & 1) * 8;
                ldsm4(b1f[bh], &sm[G1_B1(cur) + row * SPH + col]);
                ldsm4(b3f[bh], &sm[G1_B3(cur) + row * SPH + col]);
            }
#pragma unroll
            for (int mt = 0; mt < 4; mt++)
#pragma unroll
                for (int nt = 0; nt < 4; nt++) {
                    int bh = nt >> 1, pr = (nt & 1) * 2;
                    mma16(acc1[mt][nt], a[mt], b1f[bh][pr], b1f[bh][pr + 1]);
                    mma16(acc3[mt][nt], a[mt], b3f[bh][pr], b3f[bh][pr + 1]);
                }
        }

        if (more) {
            *(uint2*)&sm[G1_B1(nxt) + (br + 32) * SPH + bcb]     = f4h(v1a);
            *(uint2*)&sm[G1_B1(nxt) + (br + 32) * SPH + bcb + 4] = f4h(v1b);
            *(uint2*)&sm[G1_B3(nxt) + (br + 32) * SPH + bcb]     = f4h(v3a);
            *(uint2*)&sm[G1_B3(nxt) + (br + 32) * SPH + bcb + 4] = f4h(v3b);
            CP_WAIT0();
            __syncthreads();
            cur = nxt;
        }
    }

    // ---- epilogue: SwiGLU -> g_mid (fp16) ----
    const int g = lane >> 2, tg = lane & 3;
#pragma unroll
    for (int mt = 0; mt < 4; mt++)
#pragma unroll
        for (int half = 0; half < 2; half++) {
            int m = m0 + wm + mt * 16 + g + half * 8;
            if (m >= ne) continue;
            __half* dst = g_mid + ((size_t)e * T + m) * F + n0 + wn;
#pragma unroll
            for (int nt = 0; nt < 4; nt++) {
                float h0 = acc1[mt][nt][half * 2 + 0];
                float h1 = acc1[mt][nt][half * 2 + 1];
                float g0 = acc3[mt][nt][half * 2 + 0];
                float g1 = acc3[mt][nt][half * 2 + 1];
                float r0 = h0 / (1.f + __expf(-h0)) * g0;
                float r1 = h1 / (1.f + __expf(-h1)) * g1;
                *(__half2*)(dst + nt * 8 + tg * 2) = __floats2half2_rn(r0, r1);
            }
        }
}

// ---------------------------------------------------------------
// GEMM2: block 128x128, 128 thr, 4 warps (2m x 2n), warp 64x64.
// out[tok] += weight * (mid . w2^T)
__global__ __launch_bounds__(128, 2) void gemm2_kernel(
    const float* __restrict__ w2,
    float* __restrict__ out)
{
    extern __shared__ __align__(16) __half sm[];
    const int e  = blockIdx.z;
    const int n0 = blockIdx.x * BN2;
    const int m0 = blockIdx.y * BM2;
    const int ne = g_cnt[e];
    if (m0 >= ne) return;

    const int tid  = threadIdx.x;
    const int lane = tid & 31, wid = tid >> 5;
    const int wm   = (wid & 1) * 64, wn = (wid >> 1) * 64;

    const __half* amb = g_mid + ((size_t)e * T + m0) * F;
    // A loader (cp.async, 4/thread): row = tid>>2 + 32r, col8 = (tid&3)*8
    const int ar = tid >> 2, ac8 = (tid & 3) * 8;
    // B loader (two waves of 64 rows): row = tid>>1, colbase = (tid&1)*16; 4 f4 per wave
    const int br = tid >> 1, bcb = (tid & 1) * 16;
    const float* bp = w2 + ((size_t)e * H + n0 + br) * F + bcb;
    const size_t bw = (size_t)64 * F;

    float4 vB[4];
    float acc[4][8][4] = {};

    // ---- prologue ----
#pragma unroll
    for (int r = 0; r < 4; r++)
        cp_async16(&sm[G2_A(0) + (ar + 32 * r) * SPH + ac8],
                   amb + (size_t)(ar + 32 * r) * F + ac8);
    CP_COMMIT();
#pragma unroll
    for (int w = 0; w < 2; w++) {
#pragma unroll
        for (int j = 0; j < 4; j++) vB[j] = *(const float4*)(bp + w * bw + j * 4);
#pragma unroll
        for (int j = 0; j < 4; j++)
            *(uint2*)&sm[G2_B(0) + (br + 64 * w) * SPH + bcb + j * 4] = f4h(vB[j]);
    }
    CP_WAIT0();
    __syncthreads();

    const int NC = F / BK2;   // 64
    int cur = 0;
    for (int c = 0; c < NC; c++) {
        const int  nxt  = cur ^ 1;
        const bool more = (c + 1 < NC);
        int k0 = (c + 1) * BK2;
        if (more) {
#pragma unroll
            for (int r = 0; r < 4; r++)
                cp_async16(&sm[G2_A(nxt) + (ar + 32 * r) * SPH + ac8],
                           amb + (size_t)(ar + 32 * r) * F + k0 + ac8);
            CP_COMMIT();
#pragma unroll
            for (int j = 0; j < 4; j++) vB[j] = *(const float4*)(bp + k0 + j * 4);
        }

        // ---- compute kk=0 ----
        {
            unsigned a[4][4];
#pragma unroll
            for (int mt = 0; mt < 4; mt++)
                ldsm4(a[mt], &sm[G2_A(cur) + (wm + mt * 16 + (lane & 15)) * SPH + (lane >> 4) * 8]);
            unsigned bf[4][4];
#pragma unroll
            for (int bh = 0; bh < 4; bh++) {
                int row = wn + bh * 16 + ((lane >> 4) & 1) * 8 + (lane & 7);
                int col = ((lane >> 3) & 1) * 8;
                ldsm4(bf[bh], &sm[G2_B(cur) + row * SPH + col]);
            }
#pragma unroll
            for (int mt = 0; mt < 4; mt++)
#pragma unroll
                for (int nt = 0; nt < 8; nt++) {
                    int bh = nt >> 1, pr = (nt & 1) * 2;
                    mma16(acc[mt][nt], a[mt], bf[bh][pr], bf[bh][pr + 1]);
                }
        }

        if (more) {
            // store wave0, load wave1
#pragma unroll
            for (int j = 0; j < 4; j++)
                *(uint2*)&sm[G2_B(nxt) + br * SPH + bcb + j * 4] = f4h(vB[j]);
#pragma unroll
            for (int j = 0; j < 4; j++) vB[j] = *(const float4*)(bp + bw + k0 + j * 4);
        }

        // ---- compute kk=16 ----
        {
            unsigned a[4][4];
#pragma unroll
            for (int mt = 0; mt < 4; mt++)
                ldsm4(a[mt], &sm[G2_A(cur) + (wm + mt * 16 + (lane & 15)) * SPH + 16 + (lane >> 4) * 8]);
            unsigned bf[4][4];
#pragma unroll
            for (int bh = 0; bh < 4; bh++) {
                int row = wn + bh * 16 + ((lane >> 4) & 1) * 8 + (lane & 7);
                int col = 16 + ((lane >> 3) & 1) * 8;
                ldsm4(bf[bh], &sm[G2_B(cur) + row * SPH + col]);
            }
#pragma unroll
            for (int mt = 0; mt < 4; mt++)
#pragma unroll
                for (int nt = 0; nt < 8; nt++) {
                    int bh = nt >> 1, pr = (nt & 1) * 2;
                    mma16(acc[mt][nt], a[mt], bf[bh][pr], bf[bh][pr + 1]);
                }
        }

        if (more) {
#pragma unroll
            for (int j = 0; j < 4; j++)
                *(uint2*)&sm[G2_B(nxt) + (br + 64) * SPH + bcb + j * 4] = f4h(vB[j]);
            CP_WAIT0();
            __syncthreads();
            cur = nxt;
        }
    }

    // ---- epilogue: weighted atomic scatter ----
    const int g = lane >> 2, tg = lane & 3;
#pragma unroll
    for (int mt = 0; mt < 4; mt++)
#pragma unroll
        for (int half = 0; half < 2; half++) {
            int m = m0 + wm + mt * 16 + g + half * 8;
            if (m >= ne) continue;
            int   tok = g_tok[e * T + m];
            float w   = g_wgt[e * T + m];
            float* dst = out + (size_t)tok * H + n0 + wn;
#pragma unroll
            for (int nt = 0; nt < 8; nt++) {
                atomicAdd(dst + nt * 8 + tg * 2 + 0, w * acc[mt][nt][half * 2 + 0]);
                atomicAdd(dst + nt * 8 + tg * 2 + 1, w * acc[mt][nt][half * 2 + 1]);
            }
        }
}

// ---------------------------------------------------------------
extern "C" void kernel_launch(void* const* d_in, const int* in_sizes, int n_in,
                              void* d_out, int out_size)
{
    const float* x  = (const float*)d_in[0];
    const float* gw = (const float*)d_in[1];
    const float* w1 = (const float*)d_in[2];
    const float* w2 = (const float*)d_in[3];
    const float* w3 = (const float*)d_in[4];
    float* out = (float*)d_out;

    static int configured = 0;
    if (!configured) {
        cudaFuncSetAttribute(gemm1_kernel,
            cudaFuncAttributeMaxDynamicSharedMemorySize, G1_BYTES);
        cudaFuncSetAttribute(gemm2_kernel,
            cudaFuncAttributeMaxDynamicSharedMemorySize, G2_BYTES);
        configured = 1;
    }

    const size_t main_sz = (size_t)T * H;
    float* logits = ((size_t)out_size >= main_sz + (size_t)T * E)
                        ? out + main_sz : nullptr;

    cudaMemsetAsync(d_out, 0, (size_t)out_size * sizeof(float));
    zero_cnt_kernel<<<1, 32>>>();
    router_kernel<<<T / 8, 256>>>(x, gw, logits);
    gemm1_kernel<<<dim3(F / BN, T / BM, E), 128, G1_BYTES>>>(w1, w3);
    gemm2_kernel<<<dim3(H / BN2, T / BM2, E), 128, G2_BYTES>>>(w2, out);
}

// round 12
// speedup vs baseline: 1.6261x; 1.6261x over previous
#include <cuda_runtime.h>
#include <cuda_fp16.h>
#include <math.h>
#include <stdint.h>

#define H 1024
#define F 2048
#define E 8
#define T 2048

// ---- gemm1 tiles (R6) ----
#define BM 128
#define BN 64
#define BK 32
#define SPH 40   // smem row stride in halfs; conflict-free for ldmatrix

// ---- gemm2 tiles (R6) ----
#define BM2 128
#define BN2 128
#define BK2 32

// ---- scratch (device globals: allocation-free per harness rules) ----
__device__ int    g_cnt[E];
__device__ int    g_tok[E * T];
__device__ float  g_wgt[E * T];
__device__ __half g_mid[(size_t)E * T * F];   // [E][T][F] fp16 compacted rows
__device__ __half g_w2h[(size_t)E * H * F];   // fp16 copy of w2 (filled by gemm1 prologue)

// ---------------------------------------------------------------
__device__ __forceinline__ void ldsm4(unsigned r[4], const __half* p) {
    unsigned a = (unsigned)__cvta_generic_to_shared(p);
    asm volatile("ldmatrix.sync.aligned.m8n8.x4.shared.b16 {%0,%1,%2,%3}, [%4];"
                 : "=r"(r[0]), "=r"(r[1]), "=r"(r[2]), "=r"(r[3]) : "r"(a));
}
__device__ __forceinline__ void mma16(float c[4], const unsigned a[4], unsigned b0, unsigned b1) {
    asm volatile(
        "mma.sync.aligned.m16n8k16.row.col.f32.f16.f16.f32 "
        "{%0,%1,%2,%3},{%4,%5,%6,%7},{%8,%9},{%0,%1,%2,%3};"
        : "+f"(c[0]), "+f"(c[1]), "+f"(c[2]), "+f"(c[3])
        : "r"(a[0]), "r"(a[1]), "r"(a[2]), "r"(a[3]), "r"(b0), "r"(b1));
}
__device__ __forceinline__ uint2 f4h(float4 v) {
    __half2 lo = __floats2half2_rn(v.x, v.y);
    __half2 hi = __floats2half2_rn(v.z, v.w);
    uint2 r;
    r.x = *(unsigned*)&lo; r.y = *(unsigned*)&hi;
    return r;
}
__device__ __forceinline__ void cp_async16(const __half* sdst, const __half* gsrc) {
    unsigned d = (unsigned)__cvta_generic_to_shared(sdst);
    asm volatile("cp.async.cg.shared.global [%0], [%1], 16;" :: "r"(d), "l"(gsrc));
}
#define CP_COMMIT() asm volatile("cp.async.commit_group;" ::: "memory")
#define CP_WAIT0()  asm volatile("cp.async.wait_group 0;" ::: "memory")

// ---------------------------------------------------------------
__global__ void zero_cnt_kernel() {
    if (threadIdx.x < E) g_cnt[threadIdx.x] = 0;
}

// ---------------------------------------------------------------
// Router: one warp per token. (R6 version, unchanged)
__global__ __launch_bounds__(256) void router_kernel(
    const float* __restrict__ x, const float* __restrict__ gw,
    float* __restrict__ logits_out)
{
    const int t    = blockIdx.x * 8 + (threadIdx.x >> 5);
    const int lane = threadIdx.x & 31;
    const float4* xr  = (const float4*)(x + (size_t)t * H);
    const float4* gw4 = (const float4*)gw;

    float acc[E];
#pragma unroll
    for (int e = 0; e < E; e++) acc[e] = 0.f;

#pragma unroll
    for (int i = 0; i < 8; i++) {
        float4 xv = xr[i * 32 + lane];
#pragma unroll
        for (int e = 0; e < E; e++) {
            float4 g = gw4[e * 256 + i * 32 + lane];
            acc[e] += xv.x * g.x + xv.y * g.y + xv.z * g.z + xv.w * g.w;
        }
    }
#pragma unroll
    for (int e = 0; e < E; e++)
#pragma unroll
        for (int o = 16; o > 0; o >>= 1)
            acc[e] += __shfl_xor_sync(0xffffffffu, acc[e], o);

    if (lane == 0) {
        if (logits_out)
#pragma unroll
            for (int e = 0; e < E; e++) logits_out[(size_t)t * E + e] = acc[e];
        int i1 = 0;
#pragma unroll
        for (int e = 1; e < E; e++) if (acc[e] > acc[i1]) i1 = e;
        int i2 = -1;
#pragma unroll
        for (int e = 0; e < E; e++) {
            if (e == i1) continue;
            if (i2 < 0 || acc[e] > acc[i2]) i2 = e;
        }
        float wa = 1.f / (1.f + expf(acc[i2] - acc[i1]));
        float wb = 1.f - wa;
        int s1 = atomicAdd(&g_cnt[i1], 1);
        g_tok[i1 * T + s1] = t; g_wgt[i1 * T + s1] = wa;
        int s2 = atomicAdd(&g_cnt[i2], 1);
        g_tok[i2 * T + s2] = t; g_wgt[i2 * T + s2] = wb;
    }
}

// ---------------------------------------------------------------
// GEMM1 (R6 structure) + fused w2 fp32->fp16 conversion prologue.
// Grid must be exactly 4096 blocks: each converts 1024 float4 of w2.
__global__ __launch_bounds__(256, 2) void gemm1_kernel(
    const float* __restrict__ x,
    const float* __restrict__ w1,
    const float* __restrict__ w3,
    const float* __restrict__ w2)
{
    const int tid  = threadIdx.x;

    // ---- w2 conversion share (before any early exit) ----
    {
        int bflat = blockIdx.x + gridDim.x * (blockIdx.y + gridDim.y * blockIdx.z);
        const float4* src = (const float4*)w2 + (size_t)bflat * 1024;
        uint2* dst = (uint2*)g_w2h + (size_t)bflat * 1024;
#pragma unroll
        for (int j = 0; j < 4; j++)
            dst[j * 256 + tid] = f4h(src[j * 256 + tid]);
    }

    const int e  = blockIdx.z;
    const int n0 = blockIdx.x * BN;
    const int m0 = blockIdx.y * BM;
    const int ne = g_cnt[e];
    if (m0 >= ne) return;

    __shared__ __align__(16) __half sA [2][BM * SPH];
    __shared__ __align__(16) __half sB1[2][BN * SPH];
    __shared__ __align__(16) __half sB3[2][BN * SPH];

    const int lane = tid & 31, wid = tid >> 5;
    const int wm   = (wid & 3) * 32, wn = (wid >> 2) * 32;

    const int lrow = tid >> 3, lc4 = tid & 7;

    const float* ap[4];
#pragma unroll
    for (int r = 0; r < 4; r++) {
        int m = m0 + lrow + 32 * r;
        int idx = (m < ne) ? m : (ne - 1);
        ap[r] = x + (size_t)g_tok[e * T + idx] * H + lc4 * 4;
    }
    const float* b1p[2];
    const float* b3p[2];
#pragma unroll
    for (int r = 0; r < 2; r++) {
        b1p[r] = w1 + ((size_t)e * F + n0 + lrow + 32 * r) * H + lc4 * 4;
        b3p[r] = w3 + ((size_t)e * F + n0 + lrow + 32 * r) * H + lc4 * 4;
    }

    float4 va[4], vb1[2], vb3[2];
    float acc1[2][4][4] = {}, acc3[2][4][4] = {};

#pragma unroll
    for (int r = 0; r < 4; r++) va[r] = *(const float4*)(ap[r]);
#pragma unroll
    for (int r = 0; r < 2; r++) { vb1[r] = *(const float4*)(b1p[r]); vb3[r] = *(const float4*)(b3p[r]); }
#pragma unroll
    for (int r = 0; r < 4; r++) *(uint2*)&sA[0][(lrow + 32 * r) * SPH + lc4 * 4] = f4h(va[r]);
#pragma unroll
    for (int r = 0; r < 2; r++) {
        *(uint2*)&sB1[0][(lrow + 32 * r) * SPH + lc4 * 4] = f4h(vb1[r]);
        *(uint2*)&sB3[0][(lrow + 32 * r) * SPH + lc4 * 4] = f4h(vb3[r]);
    }
    __syncthreads();

    int cur = 0;
    for (int chunk = 1; chunk <= H / BK; chunk++) {
        if (chunk < H / BK) {
            int k0 = chunk * BK;
#pragma unroll
            for (int r = 0; r < 4; r++) va[r] = *(const float4*)(ap[r] + k0);
#pragma unroll
            for (int r = 0; r < 2; r++) { vb1[r] = *(const float4*)(b1p[r] + k0); vb3[r] = *(const float4*)(b3p[r] + k0); }
        }
#pragma unroll
        for (int kk = 0; kk < BK; kk += 16) {
            unsigned a[2][4];
#pragma unroll
            for (int mt = 0; mt < 2; mt++)
                ldsm4(a[mt], &sA[cur][(wm + mt * 16 + (lane & 15)) * SPH + kk + (lane >> 4) * 8]);
            unsigned b1f[2][4], b3f[2][4];
#pragma unroll
            for (int bh = 0; bh < 2; bh++) {
                int row = wn + bh * 16 + ((lane >> 4) & 1) * 8 + (lane & 7);
                int col = kk + ((lane >> 3) & 1) * 8;
                ldsm4(b1f[bh], &sB1[cur][row * SPH + col]);
                ldsm4(b3f[bh], &sB3[cur][row * SPH + col]);
            }
#pragma unroll
            for (int mt = 0; mt < 2; mt++)
#pragma unroll
                for (int nt = 0; nt < 4; nt++) {
                    int bh = nt >> 1, pr = (nt & 1) * 2;
                    mma16(acc1[mt][nt], a[mt], b1f[bh][pr], b1f[bh][pr + 1]);
                    mma16(acc3[mt][nt], a[mt], b3f[bh][pr], b3f[bh][pr + 1]);
                }
        }
        if (chunk < H / BK) {
            int nxt = cur ^ 1;
#pragma unroll
            for (int r = 0; r < 4; r++) *(uint2*)&sA[nxt][(lrow + 32 * r) * SPH + lc4 * 4] = f4h(va[r]);
#pragma unroll
            for (int r = 0; r < 2; r++) {
                *(uint2*)&sB1[nxt][(lrow + 32 * r) * SPH + lc4 * 4] = f4h(vb1[r]);
                *(uint2*)&sB3[nxt][(lrow + 32 * r) * SPH + lc4 * 4] = f4h(vb3[r]);
            }
            __syncthreads();
            cur = nxt;
        }
    }

    const int g = lane >> 2, tg = lane & 3;
#pragma unroll
    for (int mt = 0; mt < 2; mt++)
#pragma unroll
        for (int half = 0; half < 2; half++) {
            int m = m0 + wm + mt * 16 + g + half * 8;
            if (m >= ne) continue;
            __half* dst = g_mid + ((size_t)e * T + m) * F + n0 + wn;
#pragma unroll
            for (int nt = 0; nt < 4; nt++) {
                float h0 = acc1[mt][nt][half * 2 + 0];
                float h1 = acc1[mt][nt][half * 2 + 1];
                float g0 = acc3[mt][nt][half * 2 + 0];
                float g1 = acc3[mt][nt][half * 2 + 1];
                float r0 = h0 / (1.f + __expf(-h0)) * g0;
                float r1 = h1 / (1.f + __expf(-h1)) * g1;
                __half2 v = __floats2half2_rn(r0, r1);
                *(__half2*)(dst + nt * 8 + tg * 2) = v;
            }
        }
}

// ---------------------------------------------------------------
// GEMM2 (R6 tiles): A AND B both via cp.async (fp16 g_mid / g_w2h).
// out[tok] += weight * (mid . w2^T)
__global__ __launch_bounds__(256, 2) void gemm2_kernel(
    float* __restrict__ out)
{
    const int e  = blockIdx.z;
    const int n0 = blockIdx.x * BN2;
    const int m0 = blockIdx.y * BM2;
    const int ne = g_cnt[e];
    if (m0 >= ne) return;

    __shared__ __align__(16) __half sA[2][BM2 * SPH];
    __shared__ __align__(16) __half sB[2][BN2 * SPH];

    const int tid  = threadIdx.x;
    const int lane = tid & 31, wid = tid >> 5;
    const int wm   = (wid & 3) * 32, wn = (wid >> 2) * 64;

    // A loader (cp.async, 2/thread): rows arow, arow+64; col8 = (tid&3)*8
    const int arow = tid >> 2, ac8 = (tid & 3) * 8;
    const __half* amp0 = g_mid + ((size_t)e * T + m0 + arow) * F + ac8;
    const __half* amp1 = g_mid + ((size_t)e * T + m0 + arow + 64) * F + ac8;

    // B loader (cp.async, 2/thread): row = tid>>1, granules at col {bco, bco+16}
    const int brow = tid >> 1, bco = (tid & 1) * 8;
    const __half* bmb = g_w2h + ((size_t)e * H + n0 + brow) * F + bco;

    float acc[2][8][4] = {};

    // ---- prologue ----
    cp_async16(&sA[0][arow * SPH + ac8],        amp0);
    cp_async16(&sA[0][(arow + 64) * SPH + ac8], amp1);
    cp_async16(&sB[0][brow * SPH + bco],        bmb);
    cp_async16(&sB[0][brow * SPH + bco + 16],   bmb + 16);
    CP_COMMIT();
    CP_WAIT0();
    __syncthreads();

    const int NC = F / BK2;   // 64
    int cur = 0;
    for (int c = 0; c < NC; c++) {
        const int nxt = cur ^ 1;
        const bool more = (c + 1 < NC);
        if (more) {
            int k0 = (c + 1) * BK2;
            cp_async16(&sA[nxt][arow * SPH + ac8],        amp0 + k0);
            cp_async16(&sA[nxt][(arow + 64) * SPH + ac8], amp1 + k0);
            cp_async16(&sB[nxt][brow * SPH + bco],        bmb + k0);
            cp_async16(&sB[nxt][brow * SPH + bco + 16],   bmb + k0 + 16);
            CP_COMMIT();
        }

        // ---- compute on cur ----
#pragma unroll
        for (int kk = 0; kk < BK2; kk += 16) {
            unsigned a[2][4];
#pragma unroll
            for (int mt = 0; mt < 2; mt++)
                ldsm4(a[mt], &sA[cur][(wm + mt * 16 + (lane & 15)) * SPH + kk + (lane >> 4) * 8]);
            unsigned bf[4][4];
#pragma unroll
            for (int bh = 0; bh < 4; bh++) {
                int row = wn + bh * 16 + ((lane >> 4) & 1) * 8 + (lane & 7);
                int col = kk + ((lane >> 3) & 1) * 8;
                ldsm4(bf[bh], &sB[cur][row * SPH + col]);
            }
#pragma unroll
            for (int mt = 0; mt < 2; mt++)
#pragma unroll
                for (int nt = 0; nt < 8; nt++) {
                    int bh = nt >> 1, pr = (nt & 1) * 2;
                    mma16(acc[mt][nt], a[mt], bf[bh][pr], bf[bh][pr + 1]);
                }
        }

        if (more) {
            CP_WAIT0();
            __syncthreads();
            cur = nxt;
        }
    }

    // ---- epilogue: weighted atomic scatter ----
    const int g = lane >> 2, tg = lane & 3;
#pragma unroll
    for (int mt = 0; mt < 2; mt++)
#pragma unroll
        for (int half = 0; half < 2; half++) {
            int m = m0 + wm + mt * 16 + g + half * 8;
            if (m >= ne) continue;
            int   tok = g_tok[e * T + m];
            float w   = g_wgt[e * T + m];
            float* dst = out + (size_t)tok * H + n0 + wn;
#pragma unroll
            for (int nt = 0; nt < 8; nt++) {
                atomicAdd(dst + nt * 8 + tg * 2 + 0, w * acc[mt][nt][half * 2 + 0]);
                atomicAdd(dst + nt * 8 + tg * 2 + 1, w * acc[mt][nt][half * 2 + 1]);
            }
        }
}

// ---------------------------------------------------------------
extern "C" void kernel_launch(void* const* d_in, const int* in_sizes, int n_in,
                              void* d_out, int out_size)
{
    const float* x  = (const float*)d_in[0];
    const float* gw = (const float*)d_in[1];
    const float* w1 = (const float*)d_in[2];
    const float* w2 = (const float*)d_in[3];
    const float* w3 = (const float*)d_in[4];
    float* out = (float*)d_out;

    const size_t main_sz = (size_t)T * H;
    float* logits = ((size_t)out_size >= main_sz + (size_t)T * E)
                        ? out + main_sz : nullptr;

    cudaMemsetAsync(d_out, 0, (size_t)out_size * sizeof(float));
    zero_cnt_kernel<<<1, 32>>>();
    router_kernel<<<T / 8, 256>>>(x, gw, logits);
    // grid = 32*16*8 = 4096 blocks; each converts 1024 float4 of w2 (= E*H*F/4 total)
    gemm1_kernel<<<dim3(F / BN, T / BM, E), 256>>>(x, w1, w3, w2);
    gemm2_kernel<<<dim3(H / BN2, T / BM2, E), 256>>>(out);
}

// round 13
// speedup vs baseline: 1.7089x; 1.0509x over previous
#include <cuda_runtime.h>
#include <cuda_fp16.h>
#include <math.h>
#include <stdint.h>

#define H 1024
#define F 2048
#define E 8
#define T 2048

// ---- gemm1 tiles (R6/R12) ----
#define BM 128
#define BN 64
#define BK 32
#define SPH 40   // smem row stride in halfs; ldmatrix conflict-free

// ---- gemm2 tiles (R13): BK=64, 3-stage ----
#define BM2 128
#define BN2 128
#define BK2 64
#define SPH2 72  // 64 halfs + 8 pad; banks 4r%32 distinct -> conflict-free
#define NSTG2 3

#define G2_AST (BM2 * SPH2)
#define G2_BST (BN2 * SPH2)
#define G2_A(s)  ((s) * G2_AST)
#define G2_B(s)  (NSTG2 * G2_AST + (s) * G2_BST)
#define G2_BYTES ((NSTG2 * (G2_AST + G2_BST)) * 2)   // 110592

// ---- scratch (device globals: allocation-free per harness rules) ----
__device__ int    g_cnt[E];
__device__ int    g_tok[E * T];
__device__ float  g_wgt[E * T];
__device__ __half g_mid[(size_t)E * T * F];   // [E][T][F] fp16 compacted rows
__device__ __half g_w2h[(size_t)E * H * F];   // fp16 copy of w2 (filled in gemm1 prologue)

// ---------------------------------------------------------------
__device__ __forceinline__ void ldsm4(unsigned r[4], const __half* p) {
    unsigned a = (unsigned)__cvta_generic_to_shared(p);
    asm volatile("ldmatrix.sync.aligned.m8n8.x4.shared.b16 {%0,%1,%2,%3}, [%4];"
                 : "=r"(r[0]), "=r"(r[1]), "=r"(r[2]), "=r"(r[3]) : "r"(a));
}
__device__ __forceinline__ void mma16(float c[4], const unsigned a[4], unsigned b0, unsigned b1) {
    asm volatile(
        "mma.sync.aligned.m16n8k16.row.col.f32.f16.f16.f32 "
        "{%0,%1,%2,%3},{%4,%5,%6,%7},{%8,%9},{%0,%1,%2,%3};"
        : "+f"(c[0]), "+f"(c[1]), "+f"(c[2]), "+f"(c[3])
        : "r"(a[0]), "r"(a[1]), "r"(a[2]), "r"(a[3]), "r"(b0), "r"(b1));
}
__device__ __forceinline__ uint2 f4h(float4 v) {
    __half2 lo = __floats2half2_rn(v.x, v.y);
    __half2 hi = __floats2half2_rn(v.z, v.w);
    uint2 r;
    r.x = *(unsigned*)&lo; r.y = *(unsigned*)&hi;
    return r;
}
__device__ __forceinline__ void cp_async16(const __half* sdst, const __half* gsrc) {
    unsigned d = (unsigned)__cvta_generic_to_shared(sdst);
    asm volatile("cp.async.cg.shared.global [%0], [%1], 16;" :: "r"(d), "l"(gsrc));
}
#define CP_COMMIT() asm volatile("cp.async.commit_group;" ::: "memory")
#define CP_WAIT0()  asm volatile("cp.async.wait_group 0;" ::: "memory")
#define CP_WAIT1()  asm volatile("cp.async.wait_group 1;" ::: "memory")

// ---------------------------------------------------------------
__global__ void zero_cnt_kernel() {
    if (threadIdx.x < E) g_cnt[threadIdx.x] = 0;
}

// ---------------------------------------------------------------
// Router: one warp per token.
__global__ __launch_bounds__(256) void router_kernel(
    const float* __restrict__ x, const float* __restrict__ gw,
    float* __restrict__ logits_out)
{
    const int t    = blockIdx.x * 8 + (threadIdx.x >> 5);
    const int lane = threadIdx.x & 31;
    const float4* xr  = (const float4*)(x + (size_t)t * H);
    const float4* gw4 = (const float4*)gw;

    float acc[E];
#pragma unroll
    for (int e = 0; e < E; e++) acc[e] = 0.f;

#pragma unroll
    for (int i = 0; i < 8; i++) {
        float4 xv = xr[i * 32 + lane];
#pragma unroll
        for (int e = 0; e < E; e++) {
            float4 g = gw4[e * 256 + i * 32 + lane];
            acc[e] += xv.x * g.x + xv.y * g.y + xv.z * g.z + xv.w * g.w;
        }
    }
#pragma unroll
    for (int e = 0; e < E; e++)
#pragma unroll
        for (int o = 16; o > 0; o >>= 1)
            acc[e] += __shfl_xor_sync(0xffffffffu, acc[e], o);

    if (lane == 0) {
        if (logits_out)
#pragma unroll
            for (int e = 0; e < E; e++) logits_out[(size_t)t * E + e] = acc[e];
        int i1 = 0;
#pragma unroll
        for (int e = 1; e < E; e++) if (acc[e] > acc[i1]) i1 = e;
        int i2 = -1;
#pragma unroll
        for (int e = 0; e < E; e++) {
            if (e == i1) continue;
            if (i2 < 0 || acc[e] > acc[i2]) i2 = e;
        }
        float wa = 1.f / (1.f + expf(acc[i2] - acc[i1]));
        float wb = 1.f - wa;
        int s1 = atomicAdd(&g_cnt[i1], 1);
        g_tok[i1 * T + s1] = t; g_wgt[i1 * T + s1] = wa;
        int s2 = atomicAdd(&g_cnt[i2], 1);
        g_tok[i2 * T + s2] = t; g_wgt[i2 * T + s2] = wb;
    }
}

// ---------------------------------------------------------------
// GEMM1 (R6 structure) + fused w2 fp32->fp16 conversion prologue.
// Grid must be exactly 4096 blocks: each converts 1024 float4 of w2.
__global__ __launch_bounds__(256, 2) void gemm1_kernel(
    const float* __restrict__ x,
    const float* __restrict__ w1,
    const float* __restrict__ w3,
    const float* __restrict__ w2)
{
    const int tid  = threadIdx.x;

    // ---- w2 conversion share (before any early exit) ----
    {
        int bflat = blockIdx.x + gridDim.x * (blockIdx.y + gridDim.y * blockIdx.z);
        const float4* src = (const float4*)w2 + (size_t)bflat * 1024;
        uint2* dst = (uint2*)g_w2h + (size_t)bflat * 1024;
#pragma unroll
        for (int j = 0; j < 4; j++)
            dst[j * 256 + tid] = f4h(src[j * 256 + tid]);
    }

    const int e  = blockIdx.z;
    const int n0 = blockIdx.x * BN;
    const int m0 = blockIdx.y * BM;
    const int ne = g_cnt[e];
    if (m0 >= ne) return;

    __shared__ __align__(16) __half sA [2][BM * SPH];
    __shared__ __align__(16) __half sB1[2][BN * SPH];
    __shared__ __align__(16) __half sB3[2][BN * SPH];

    const int lane = tid & 31, wid = tid >> 5;
    const int wm   = (wid & 3) * 32, wn = (wid >> 2) * 32;

    const int lrow = tid >> 3, lc4 = tid & 7;

    const float* ap[4];
#pragma unroll
    for (int r = 0; r < 4; r++) {
        int m = m0 + lrow + 32 * r;
        int idx = (m < ne) ? m : (ne - 1);
        ap[r] = x + (size_t)g_tok[e * T + idx] * H + lc4 * 4;
    }
    const float* b1p[2];
    const float* b3p[2];
#pragma unroll
    for (int r = 0; r < 2; r++) {
        b1p[r] = w1 + ((size_t)e * F + n0 + lrow + 32 * r) * H + lc4 * 4;
        b3p[r] = w3 + ((size_t)e * F + n0 + lrow + 32 * r) * H + lc4 * 4;
    }

    float4 va[4], vb1[2], vb3[2];
    float acc1[2][4][4] = {}, acc3[2][4][4] = {};

#pragma unroll
    for (int r = 0; r < 4; r++) va[r] = *(const float4*)(ap[r]);
#pragma unroll
    for (int r = 0; r < 2; r++) { vb1[r] = *(const float4*)(b1p[r]); vb3[r] = *(const float4*)(b3p[r]); }
#pragma unroll
    for (int r = 0; r < 4; r++) *(uint2*)&sA[0][(lrow + 32 * r) * SPH + lc4 * 4] = f4h(va[r]);
#pragma unroll
    for (int r = 0; r < 2; r++) {
        *(uint2*)&sB1[0][(lrow + 32 * r) * SPH + lc4 * 4] = f4h(vb1[r]);
        *(uint2*)&sB3[0][(lrow + 32 * r) * SPH + lc4 * 4] = f4h(vb3[r]);
    }
    __syncthreads();

    int cur = 0;
    for (int chunk = 1; chunk <= H / BK; chunk++) {
        if (chunk < H / BK) {
            int k0 = chunk * BK;
#pragma unroll
            for (int r = 0; r < 4; r++) va[r] = *(const float4*)(ap[r] + k0);
#pragma unroll
            for (int r = 0; r < 2; r++) { vb1[r] = *(const float4*)(b1p[r] + k0); vb3[r] = *(const float4*)(b3p[r] + k0); }
        }
#pragma unroll
        for (int kk = 0; kk < BK; kk += 16) {
            unsigned a[2][4];
#pragma unroll
            for (int mt = 0; mt < 2; mt++)
                ldsm4(a[mt], &sA[cur][(wm + mt * 16 + (lane & 15)) * SPH + kk + (lane >> 4) * 8]);
            unsigned b1f[2][4], b3f[2][4];
#pragma unroll
            for (int bh = 0; bh < 2; bh++) {
                int row = wn + bh * 16 + ((lane >> 4) & 1) * 8 + (lane & 7);
                int col = kk + ((lane >> 3) & 1) * 8;
                ldsm4(b1f[bh], &sB1[cur][row * SPH + col]);
                ldsm4(b3f[bh], &sB3[cur][row * SPH + col]);
            }
#pragma unroll
            for (int mt = 0; mt < 2; mt++)
#pragma unroll
                for (int nt = 0; nt < 4; nt++) {
                    int bh = nt >> 1, pr = (nt & 1) * 2;
                    mma16(acc1[mt][nt], a[mt], b1f[bh][pr], b1f[bh][pr + 1]);
                    mma16(acc3[mt][nt], a[mt], b3f[bh][pr], b3f[bh][pr + 1]);
                }
        }
        if (chunk < H / BK) {
            int nxt = cur ^ 1;
#pragma unroll
            for (int r = 0; r < 4; r++) *(uint2*)&sA[nxt][(lrow + 32 * r) * SPH + lc4 * 4] = f4h(va[r]);
#pragma unroll
            for (int r = 0; r < 2; r++) {
                *(uint2*)&sB1[nxt][(lrow + 32 * r) * SPH + lc4 * 4] = f4h(vb1[r]);
                *(uint2*)&sB3[nxt][(lrow + 32 * r) * SPH + lc4 * 4] = f4h(vb3[r]);
            }
            __syncthreads();
            cur = nxt;
        }
    }

    const int g = lane >> 2, tg = lane & 3;
#pragma unroll
    for (int mt = 0; mt < 2; mt++)
#pragma unroll
        for (int half = 0; half < 2; half++) {
            int m = m0 + wm + mt * 16 + g + half * 8;
            if (m >= ne) continue;
            __half* dst = g_mid + ((size_t)e * T + m) * F + n0 + wn;
#pragma unroll
            for (int nt = 0; nt < 4; nt++) {
                float h0 = acc1[mt][nt][half * 2 + 0];
                float h1 = acc1[mt][nt][half * 2 + 1];
                float g0 = acc3[mt][nt][half * 2 + 0];
                float g1 = acc3[mt][nt][half * 2 + 1];
                float r0 = h0 / (1.f + __expf(-h0)) * g0;
                float r1 = h1 / (1.f + __expf(-h1)) * g1;
                __half2 v = __floats2half2_rn(r0, r1);
                *(__half2*)(dst + nt * 8 + tg * 2) = v;
            }
        }
}

// ---------------------------------------------------------------
// GEMM2 (R13): BK=64, 3 stages, 2 cp.async groups in flight.
// out[tok] += weight * (mid . w2^T); A=g_mid fp16, B=g_w2h fp16.
__global__ __launch_bounds__(256, 2) void gemm2_kernel(
    float* __restrict__ out)
{
    extern __shared__ __align__(16) __half sm[];
    const int e  = blockIdx.z;
    const int n0 = blockIdx.x * BN2;
    const int m0 = blockIdx.y * BM2;
    const int ne = g_cnt[e];
    if (m0 >= ne) return;

    const int tid  = threadIdx.x;
    const int lane = tid & 31, wid = tid >> 5;
    const int wm   = (wid & 3) * 32, wn = (wid >> 2) * 64;

    // loader mapping: 4 granules/thread each for A and B.
    //   lin = i*256+tid, row = lin>>3 (0..127), col8 = (lin&7)*8
    const int lrow = tid >> 3, lc8 = (tid & 7) * 8;
    const __half* amb = g_mid + ((size_t)e * T + m0 + lrow) * F + lc8;
    const __half* bmb = g_w2h + ((size_t)e * H + n0 + lrow) * F + lc8;

    float acc[2][8][4] = {};

    // ---- prologue: stages 0,1 in flight (2 commit groups) ----
#pragma unroll
    for (int s = 0; s < 2; s++) {
#pragma unroll
        for (int i = 0; i < 4; i++) {
            int row = lrow + 32 * i;
            cp_async16(&sm[G2_A(s) + row * SPH2 + lc8], amb + (size_t)(32 * i) * F + s * BK2);
            cp_async16(&sm[G2_B(s) + row * SPH2 + lc8], bmb + (size_t)(32 * i) * F + s * BK2);
        }
        CP_COMMIT();
    }
    CP_WAIT1();   // stage 0 ready
    __syncthreads();

    const int NC = F / BK2;   // 32
    int cur = 0;
    for (int c = 0; c < NC; c++) {
        const bool have2 = (c + 2 < NC);
        if (have2) {
            int s = (cur + 2) % NSTG2;
            int k0 = (c + 2) * BK2;
#pragma unroll
            for (int i = 0; i < 4; i++) {
                int row = lrow + 32 * i;
                cp_async16(&sm[G2_A(s) + row * SPH2 + lc8], amb + (size_t)(32 * i) * F + k0);
                cp_async16(&sm[G2_B(s) + row * SPH2 + lc8], bmb + (size_t)(32 * i) * F + k0);
            }
            CP_COMMIT();
        }

        // ---- compute on cur: 4 k-steps ----
#pragma unroll
        for (int kk = 0; kk < BK2; kk += 16) {
            unsigned a[2][4];
#pragma unroll
            for (int mt = 0; mt < 2; mt++)
                ldsm4(a[mt], &sm[G2_A(cur) + (wm + mt * 16 + (lane & 15)) * SPH2 + kk + (lane >> 4) * 8]);
            unsigned bf[4][4];
#pragma unroll
            for (int bh = 0; bh < 4; bh++) {
                int row = wn + bh * 16 + ((lane >> 4) & 1) * 8 + (lane & 7);
                int col = kk + ((lane >> 3) & 1) * 8;
                ldsm4(bf[bh], &sm[G2_B(cur) + row * SPH2 + col]);
            }
#pragma unroll
            for (int mt = 0; mt < 2; mt++)
#pragma unroll
                for (int nt = 0; nt < 8; nt++) {
                    int bh = nt >> 1, pr = (nt & 1) * 2;
                    mma16(acc[mt][nt], a[mt], bf[bh][pr], bf[bh][pr + 1]);
                }
        }

        if (c + 1 < NC) {
            if (have2) CP_WAIT1(); else CP_WAIT0();
            __syncthreads();
            cur = (cur + 1 == NSTG2) ? 0 : cur + 1;
        }
    }

    // ---- epilogue: weighted atomic scatter ----
    const int g = lane >> 2, tg = lane & 3;
#pragma unroll
    for (int mt = 0; mt < 2; mt++)
#pragma unroll
        for (int half = 0; half < 2; half++) {
            int m = m0 + wm + mt * 16 + g + half * 8;
            if (m >= ne) continue;
            int   tok = g_tok[e * T + m];
            float w   = g_wgt[e * T + m];
            float* dst = out + (size_t)tok * H + n0 + wn;
#pragma unroll
            for (int nt = 0; nt < 8; nt++) {
                atomicAdd(dst + nt * 8 + tg * 2 + 0, w * acc[mt][nt][half * 2 + 0]);
                atomicAdd(dst + nt * 8 + tg * 2 + 1, w * acc[mt][nt][half * 2 + 1]);
            }
        }
}

// ---------------------------------------------------------------
extern "C" void kernel_launch(void* const* d_in, const int* in_sizes, int n_in,
                              void* d_out, int out_size)
{
    const float* x  = (const float*)d_in[0];
    const float* gw = (const float*)d_in[1];
    const float* w1 = (const float*)d_in[2];
    const float* w2 = (const float*)d_in[3];
    const float* w3 = (const float*)d_in[4];
    float* out = (float*)d_out;

    static int configured = 0;
    if (!configured) {
        cudaFuncSetAttribute(gemm2_kernel,
            cudaFuncAttributeMaxDynamicSharedMemorySize, G2_BYTES);
        configured = 1;
    }

    const size_t main_sz = (size_t)T * H;
    float* logits = ((size_t)out_size >= main_sz + (size_t)T * E)
                        ? out + main_sz : nullptr;

    cudaMemsetAsync(d_out, 0, (size_t)out_size * sizeof(float));
    zero_cnt_kernel<<<1, 32>>>();
    router_kernel<<<T / 8, 256>>>(x, gw, logits);
    // grid = 32*16*8 = 4096 blocks; each converts 1024 float4 of w2
    gemm1_kernel<<<dim3(F / BN, T / BM, E), 256>>>(x, w1, w3, w2);
    gemm2_kernel<<<dim3(H / BN2, T / BM2, E), 256, G2_BYTES>>>(out);
}